// round 5
// baseline (speedup 1.0000x reference)
#include <cuda_runtime.h>
#include <cuda_bf16.h>
#include <math.h>
#include <stdint.h>

// Problem constants
#define BB 8
#define NN 1024
#define DD 768
#define HH 4
#define MM (BB * NN)
#define ALPHA_LRELU 0.2f

// ----------------------------------------------------------------------------
// Scratch (device globals)
// ----------------------------------------------------------------------------
__device__ float g_Xr[(long)MM * DD];                 // tf32-rounded input
__device__ float g_Wr[(long)HH * DD * DD];            // rounded W_heads (row-major)
__device__ float g_WoR[(long)HH * DD * DD];           // rounded W_out (row-major)
__device__ float g_Wh[(long)HH * MM * DD];            // per-head Wh (rounded)
__device__ float g_xx[(long)MM * (HH * DD)];          // concat heads (rounded)
__device__ float g_Who[(long)MM * DD];                // out-layer Wh (rounded)
__device__ float g_P[(long)HH * BB * NN * NN];        // attention probs (rounded)
__device__ float g_f1[HH * MM];
__device__ float g_f2[HH * MM];
__device__ float g_f1o[MM];
__device__ float g_f2o[MM];

// ----------------------------------------------------------------------------
// helpers
// ----------------------------------------------------------------------------
__device__ __forceinline__ uint32_t smem_u32(const void* p) {
    uint32_t a;
    asm("{ .reg .u64 t; cvta.to.shared.u64 t, %1; cvt.u32.u64 %0, t; }" : "=r"(a) : "l"(p));
    return a;
}
__device__ __forceinline__ float totf32(float x) {
    uint32_t u;
    asm("cvt.rna.tf32.f32 %0, %1;" : "=r"(u) : "f"(x));
    return __uint_as_float(u);
}

#define CP16(dst, src) asm volatile("cp.async.cg.shared.global [%0], [%1], 16;" :: "r"(dst), "l"(src))
#define CP_COMMIT()    asm volatile("cp.async.commit_group;" ::: "memory")
#define CP_WAIT1()     asm volatile("cp.async.wait_group 1;" ::: "memory")
#define CP_WAIT0()     asm volatile("cp.async.wait_group 0;" ::: "memory")

// ----------------------------------------------------------------------------
// tf32 mma.sync GEMM: C[M,Nc] = A[M,K] @ B[K,Nc]   (A K-major, B row-major MN)
// 128x128 CTA tile, 8 warps (64x32), KT=32, 3-stage cp.async, 2 CTAs/SM.
// Register-fragment double buffering: LDS for kk+1 overlap HMMAs for kk.
// EPI: 0 = store rounded, 1 = elu + round, 2 = elu + residual (fp32)
// ----------------------------------------------------------------------------
#define KT 32
#define STAGES 3
#define APAD 36
#define BPAD 136
#define A_TILE_F (128 * APAD)
#define B_TILE_F (KT * BPAD)
#define STAGE_F (A_TILE_F + B_TILE_F)
#define GEMM_SMEM (STAGES * STAGE_F * 4)

template <int EPI>
__global__ void __launch_bounds__(256, 2)
mma_gemm(const float* __restrict__ A, const float* __restrict__ B,
         float* __restrict__ C, const float* __restrict__ R,
         int K, int ldb, int ldc,
         long sA, long sB, long sC, long sC2, int zmod, long sR)
{
    extern __shared__ float sm[];
    uint32_t sb = smem_u32(sm);
    int tid = threadIdx.x;
    int l = tid & 31;
    int w = tid >> 5;

    int z = blockIdx.z;
    const float* Ab = A + (long)z * sA;
    const float* Bb = B + (long)z * sB;
    float* Cb = C + (long)(z % zmod) * sC + (long)(z / zmod) * sC2;
    const float* Rb = (EPI == 2) ? (R + (long)z * sR) : nullptr;

    int brow = blockIdx.y * 128;
    int bcol = blockIdx.x * 128;
    int m0 = (w & 1) * 64;
    int n0 = (w >> 1) * 32;

    float c[4][4][4];
    #pragma unroll
    for (int i = 0; i < 4; i++)
        #pragma unroll
        for (int j = 0; j < 4; j++)
            #pragma unroll
            for (int q = 0; q < 4; q++) c[i][j][q] = 0.0f;

    int nk = K / KT;

    int aRow = tid >> 3;
    int aOff = (tid & 7) * 4;
    int bRow = tid >> 5;
    int bOff = (tid & 31) * 4;

    auto load_stage = [&](int pf) {
        int buf = pf % STAGES;
        uint32_t dA = sb + (buf * STAGE_F) * 4;
        uint32_t dB = dA + A_TILE_F * 4;
        long kof = (long)pf * KT;
        #pragma unroll
        for (int i = 0; i < 4; i++) {
            int row = aRow + i * 32;
            CP16(dA + (row * APAD + aOff) * 4, Ab + (long)(brow + row) * K + kof + aOff);
        }
        #pragma unroll
        for (int i = 0; i < 4; i++) {
            int kr = bRow + i * 8;
            CP16(dB + (kr * BPAD + bOff) * 4, Bb + (kof + kr) * (long)ldb + bcol + bOff);
        }
        CP_COMMIT();
    };

    load_stage(0);
    load_stage(1);

    // per-warp fragment base rows/cols
    int fr = m0 + (l >> 2);          // A fragment row base (+ mi*16, +8)
    int fc = n0 + (l >> 2);          // B fragment col base (+ ni*8)
    int kb = l & 3;                  // fragment k-lane

    for (int s = 0; s < nk; s++) {
        if (s + 1 < nk) { CP_WAIT1(); } else { CP_WAIT0(); }
        __syncthreads();
        if (s + 2 < nk) load_stage(s + 2);

        const float* As = sm + (s % STAGES) * STAGE_F;
        const float* Bs = As + A_TILE_F;

        float af[2][4][4], bf[2][4][2];

        // load fragments for kk = 0 into buffer 0
        {
            int k0 = kb;
            #pragma unroll
            for (int mi = 0; mi < 4; mi++) {
                int r = fr + mi * 16;
                af[0][mi][0] = As[r * APAD + k0];
                af[0][mi][1] = As[(r + 8) * APAD + k0];
                af[0][mi][2] = As[r * APAD + k0 + 4];
                af[0][mi][3] = As[(r + 8) * APAD + k0 + 4];
            }
            #pragma unroll
            for (int ni = 0; ni < 4; ni++) {
                int cn = fc + ni * 8;
                bf[0][ni][0] = Bs[k0 * BPAD + cn];
                bf[0][ni][1] = Bs[(k0 + 4) * BPAD + cn];
            }
        }

        #pragma unroll
        for (int kk = 0; kk < 4; kk++) {
            int cur = kk & 1;
            int nxt = cur ^ 1;
            if (kk < 3) {
                int k0 = (kk + 1) * 8 + kb;
                #pragma unroll
                for (int mi = 0; mi < 4; mi++) {
                    int r = fr + mi * 16;
                    af[nxt][mi][0] = As[r * APAD + k0];
                    af[nxt][mi][1] = As[(r + 8) * APAD + k0];
                    af[nxt][mi][2] = As[r * APAD + k0 + 4];
                    af[nxt][mi][3] = As[(r + 8) * APAD + k0 + 4];
                }
                #pragma unroll
                for (int ni = 0; ni < 4; ni++) {
                    int cn = fc + ni * 8;
                    bf[nxt][ni][0] = Bs[k0 * BPAD + cn];
                    bf[nxt][ni][1] = Bs[(k0 + 4) * BPAD + cn];
                }
            }
            #pragma unroll
            for (int mi = 0; mi < 4; mi++)
                #pragma unroll
                for (int ni = 0; ni < 4; ni++)
                    asm volatile(
                        "mma.sync.aligned.m16n8k8.row.col.f32.tf32.tf32.f32 "
                        "{%0,%1,%2,%3}, {%4,%5,%6,%7}, {%8,%9}, {%0,%1,%2,%3};"
                        : "+f"(c[mi][ni][0]), "+f"(c[mi][ni][1]),
                          "+f"(c[mi][ni][2]), "+f"(c[mi][ni][3])
                        : "r"(__float_as_uint(af[cur][mi][0])), "r"(__float_as_uint(af[cur][mi][1])),
                          "r"(__float_as_uint(af[cur][mi][2])), "r"(__float_as_uint(af[cur][mi][3])),
                          "r"(__float_as_uint(bf[cur][ni][0])), "r"(__float_as_uint(bf[cur][ni][1])));
        }
    }

    // epilogue (row-major C)
    #pragma unroll
    for (int mi = 0; mi < 4; mi++) {
        #pragma unroll
        for (int hh = 0; hh < 2; hh++) {
            long rg = brow + m0 + mi * 16 + (l >> 2) + hh * 8;
            #pragma unroll
            for (int ni = 0; ni < 4; ni++) {
                float v0 = c[mi][ni][hh * 2 + 0];
                float v1 = c[mi][ni][hh * 2 + 1];
                if (EPI >= 1) {
                    v0 = (v0 > 0.0f) ? v0 : expm1f(v0);
                    v1 = (v1 > 0.0f) ? v1 : expm1f(v1);
                }
                if (EPI <= 1) { v0 = totf32(v0); v1 = totf32(v1); }
                long ci = rg * ldc + bcol + n0 + ni * 8 + (l & 3) * 2;
                if (EPI == 2) {
                    float2 rv = *(const float2*)&Rb[ci];
                    v0 += rv.x; v1 += rv.y;
                }
                float2 o; o.x = v0; o.y = v1;
                *(float2*)&Cb[ci] = o;
            }
        }
    }
}

// ----------------------------------------------------------------------------
// elementwise tf32-round copy
// ----------------------------------------------------------------------------
__global__ void __launch_bounds__(256)
round_copy(const float4* __restrict__ in, float4* __restrict__ out, long n4)
{
    long i = (long)blockIdx.x * 256 + threadIdx.x;
    if (i < n4) {
        float4 v = in[i];
        v.x = totf32(v.x); v.y = totf32(v.y); v.z = totf32(v.z); v.w = totf32(v.w);
        out[i] = v;
    }
}

// ----------------------------------------------------------------------------
// fast exp (FMA only)
// ----------------------------------------------------------------------------
__device__ __forceinline__ float fexp(float x) {
    float y = x * 1.4426950408889634f;
    y = fmaxf(y, -126.0f);
    float r = y + 12582912.0f;
    float fn = r - 12582912.0f;
    int   n  = (int)fn;
    float f  = y - fn;
    float p = 1.3400e-3f;
    p = fmaf(p, f, 9.6784351e-3f);
    p = fmaf(p, f, 5.5503426e-2f);
    p = fmaf(p, f, 2.4022652e-1f);
    p = fmaf(p, f, 6.9314718e-1f);
    p = fmaf(p, f, 1.0f);
    return __int_as_float(__float_as_int(p) + (n << 23));
}

// ----------------------------------------------------------------------------
// f1/f2: warp-per-(row,head) dual dot products, float4 + shuffle reduce
// ----------------------------------------------------------------------------
__global__ void __launch_bounds__(256)
fvec_kernel(const float* __restrict__ Wh, const float* __restrict__ a,
            float* __restrict__ f1, float* __restrict__ f2, int nh)
{
    int gw = (blockIdx.x * 256 + threadIdx.x) >> 5;
    int l = threadIdx.x & 31;
    if (gw >= MM * nh) return;
    int h = gw / MM;
    const float4* wv = (const float4*)(Wh + (long)gw * DD);
    const float4* a1 = (const float4*)(a + (long)h * 2 * DD);
    const float4* a2 = (const float4*)(a + (long)h * 2 * DD + DD);
    float s1 = 0.0f, s2 = 0.0f;
    #pragma unroll
    for (int i = 0; i < DD / 128; i++) {
        int idx = l + i * 32;
        float4 v = wv[idx], x = a1[idx], y = a2[idx];
        s1 += v.x * x.x + v.y * x.y + v.z * x.z + v.w * x.w;
        s2 += v.x * y.x + v.y * y.y + v.z * y.z + v.w * y.w;
    }
    #pragma unroll
    for (int o = 16; o; o >>= 1) {
        s1 += __shfl_xor_sync(0xFFFFFFFFu, s1, o);
        s2 += __shfl_xor_sync(0xFFFFFFFFu, s2, o);
    }
    if (l == 0) { f1[gw] = s1; f2[gw] = s2; }
}

// ----------------------------------------------------------------------------
// masked softmax rows -> P (rounded); scores kept in registers
// ----------------------------------------------------------------------------
__global__ void __launch_bounds__(256)
attn_rows_kernel(const int* __restrict__ adj,
                 const float* __restrict__ f1, const float* __restrict__ f2,
                 float* __restrict__ P, int nheads)
{
    int r = blockIdx.x;
    int b = r >> 10;
    int t = threadIdx.x;
    int l = t & 31, w = t >> 5;

    __shared__ float wmax[8];
    __shared__ float wsum[8];

    int av[NN / 256];
    const int* arow = adj + (long)r * NN;
    #pragma unroll
    for (int k = 0; k < NN / 256; k++) av[k] = arow[t + k * 256];

    for (int h = 0; h < nheads; h++) {
        float f1v = f1[(long)h * MM + r];
        const float* f2h = f2 + (long)h * MM + (long)b * NN;

        float sv[NN / 256];
        float lmax = -INFINITY;
        #pragma unroll
        for (int k = 0; k < NN / 256; k++) {
            float s = f1v + f2h[t + k * 256];
            s = (s > 0.0f) ? s : ALPHA_LRELU * s;
            sv[k] = s;
            if (av[k]) lmax = fmaxf(lmax, s);
        }
        #pragma unroll
        for (int o = 16; o; o >>= 1)
            lmax = fmaxf(lmax, __shfl_xor_sync(0xFFFFFFFFu, lmax, o));
        if (l == 0) wmax[w] = lmax;
        __syncthreads();
        float m = wmax[0];
        #pragma unroll
        for (int q = 1; q < 8; q++) m = fmaxf(m, wmax[q]);

        float lsum = 0.0f;
        #pragma unroll
        for (int k = 0; k < NN / 256; k++) {
            float e = av[k] ? fexp(sv[k] - m) : 0.0f;
            sv[k] = e;
            lsum += e;
        }
        #pragma unroll
        for (int o = 16; o; o >>= 1)
            lsum += __shfl_xor_sync(0xFFFFFFFFu, lsum, o);
        if (l == 0) wsum[w] = lsum;
        __syncthreads();
        float den = 0.0f;
        #pragma unroll
        for (int q = 0; q < 8; q++) den += wsum[q];
        float rd = 1.0f / den;

        float* Prow = P + (((long)h * BB + b) * NN + (r & 1023)) * NN;
        #pragma unroll
        for (int k = 0; k < NN / 256; k++) Prow[t + k * 256] = totf32(sv[k] * rd);
    }
}

// ----------------------------------------------------------------------------
// classifier: warp-per-row
// ----------------------------------------------------------------------------
__global__ void __launch_bounds__(256)
classifier_kernel(const float* __restrict__ yy, const float* __restrict__ wc,
                  const float* __restrict__ bc, const float* __restrict__ mask,
                  float* __restrict__ scores)
{
    int gw = (blockIdx.x * 256 + threadIdx.x) >> 5;
    int l = threadIdx.x & 31;
    if (gw >= MM) return;
    const float4* y = (const float4*)(yy + (long)gw * DD);
    const float4* wv = (const float4*)wc;
    float s = 0.0f;
    #pragma unroll
    for (int i = 0; i < DD / 128; i++) {
        int idx = l + i * 32;
        float4 a = y[idx], b = wv[idx];
        s += a.x * b.x + a.y * b.y + a.z * b.z + a.w * b.w;
    }
    #pragma unroll
    for (int o = 16; o; o >>= 1) s += __shfl_xor_sync(0xFFFFFFFFu, s, o);
    if (l == 0) {
        float v = s + bc[0];
        scores[gw] = (1.0f / (1.0f + expf(-v))) * mask[gw];
    }
}

// ----------------------------------------------------------------------------
// launch
// ----------------------------------------------------------------------------
extern "C" void kernel_launch(void* const* d_in, const int* in_sizes, int n_in,
                              void* d_out, int out_size)
{
    const float* input_emb = (const float*)d_in[0];
    const int*   adj       = (const int*)d_in[1];
    const float* mask_node = (const float*)d_in[2];
    const float* W_heads   = (const float*)d_in[3];
    const float* a_heads   = (const float*)d_in[4];
    const float* W_out     = (const float*)d_in[5];
    const float* a_out     = (const float*)d_in[6];
    const float* w_cls     = (const float*)d_in[7];
    const float* b_cls     = (const float*)d_in[8];

    float* yy     = (float*)d_out;
    float* scores = (float*)d_out + (long)MM * DD;

    float *p_Xr, *p_Wr, *p_WoR, *p_Wh, *p_xx, *p_Who, *p_P;
    float *p_f1, *p_f2, *p_f1o, *p_f2o;
    cudaGetSymbolAddress((void**)&p_Xr,  g_Xr);
    cudaGetSymbolAddress((void**)&p_Wr,  g_Wr);
    cudaGetSymbolAddress((void**)&p_WoR, g_WoR);
    cudaGetSymbolAddress((void**)&p_Wh,  g_Wh);
    cudaGetSymbolAddress((void**)&p_xx,  g_xx);
    cudaGetSymbolAddress((void**)&p_Who, g_Who);
    cudaGetSymbolAddress((void**)&p_P,   g_P);
    cudaGetSymbolAddress((void**)&p_f1,  g_f1);
    cudaGetSymbolAddress((void**)&p_f2,  g_f2);
    cudaGetSymbolAddress((void**)&p_f1o, g_f1o);
    cudaGetSymbolAddress((void**)&p_f2o, g_f2o);

    cudaFuncSetAttribute(mma_gemm<0>, cudaFuncAttributeMaxDynamicSharedMemorySize, GEMM_SMEM);
    cudaFuncSetAttribute(mma_gemm<1>, cudaFuncAttributeMaxDynamicSharedMemorySize, GEMM_SMEM);
    cudaFuncSetAttribute(mma_gemm<2>, cudaFuncAttributeMaxDynamicSharedMemorySize, GEMM_SMEM);

    const int ZBIG = 1 << 30;

    // 0) tf32-round X, W_heads, W_out
    {
        long n4 = (long)MM * DD / 4;
        round_copy<<<(unsigned)((n4 + 255) / 256), 256>>>((const float4*)input_emb, (float4*)p_Xr, n4);
        long w4 = (long)HH * DD * DD / 4;
        round_copy<<<(unsigned)((w4 + 255) / 256), 256>>>((const float4*)W_heads, (float4*)p_Wr, w4);
        round_copy<<<(unsigned)((w4 + 255) / 256), 256>>>((const float4*)W_out, (float4*)p_WoR, w4);
    }

    // 1) Wh[h] = Xr @ Wr[h]
    mma_gemm<0><<<dim3(DD / 128, MM / 128, HH), 256, GEMM_SMEM>>>(
        p_Xr, p_Wr, p_Wh, nullptr, DD, DD, DD,
        0L, (long)DD * DD, (long)MM * DD, 0L, ZBIG, 0L);

    // 2) f1/f2
    fvec_kernel<<<(MM * HH * 32 + 255) / 256, 256>>>(p_Wh, a_heads, p_f1, p_f2, HH);

    // 3) attention probs
    attn_rows_kernel<<<MM, 256>>>(adj, p_f1, p_f2, p_P, HH);

    // 4) xx = elu(P @ Wh)
    mma_gemm<1><<<dim3(DD / 128, NN / 128, HH * BB), 256, GEMM_SMEM>>>(
        p_P, p_Wh, p_xx, nullptr, NN, DD, HH * DD,
        (long)NN * NN, (long)NN * DD,
        (long)NN * HH * DD, (long)DD, BB, 0L);

    // 5) Who = xx @ W_out
    mma_gemm<0><<<dim3(DD / 128, MM / 128, 1), 256, GEMM_SMEM>>>(
        p_xx, p_WoR, p_Who, nullptr, HH * DD, DD, DD,
        0L, 0L, 0L, 0L, ZBIG, 0L);

    // 6) f1o/f2o
    fvec_kernel<<<(MM * 32 + 255) / 256, 256>>>(p_Who, a_out, p_f1o, p_f2o, 1);

    // 7) out-layer attention probs
    attn_rows_kernel<<<MM, 256>>>(adj, p_f1o, p_f2o, p_P, 1);

    // 8) yy = elu(P @ Who) + input_emb
    mma_gemm<2><<<dim3(DD / 128, NN / 128, BB), 256, GEMM_SMEM>>>(
        p_P, p_Who, yy, input_emb, NN, DD, DD,
        (long)NN * NN, (long)NN * DD,
        (long)NN * DD, 0L, ZBIG, (long)NN * DD);

    // 9) classifier
    classifier_kernel<<<(MM * 32 + 255) / 256, 256>>>(yy, w_cls, b_cls, mask_node, scores);

    (void)in_sizes; (void)n_in; (void)out_size;
}

// round 6
// speedup vs baseline: 1.3012x; 1.3012x over previous
#include <cuda_runtime.h>
#include <cuda_fp16.h>
#include <math.h>
#include <stdint.h>

// Problem constants
#define BB 8
#define NN 1024
#define DD 768
#define HH 4
#define MM (BB * NN)
#define ALPHA_LRELU 0.2f

// ----------------------------------------------------------------------------
// Scratch (device globals)
// ----------------------------------------------------------------------------
__device__ __half g_X16[(long)MM * DD];                 // input as fp16 [M][K]
__device__ __half g_W16T[(long)HH * DD * DD];           // W_heads^T fp16 [h][N][K]
__device__ __half g_Wo16T[(long)DD * HH * DD];          // W_out^T fp16 [N=768][K=3072]
__device__ float  g_Wh[(long)HH * MM * DD];             // per-head Wh fp32 (fvec src)
__device__ __half g_WhT16[(long)HH * BB * DD * NN];     // Wh^T fp16 per (h,b) [d][node]
__device__ __half g_xx16[(long)MM * (HH * DD)];         // concat heads fp16 [M][3072]
__device__ float  g_Who[(long)MM * DD];                 // out-layer Wh fp32
__device__ __half g_WhoT16[(long)BB * DD * NN];         // Who^T fp16 per b
__device__ __half g_P16[(long)HH * BB * NN * NN];       // attention probs fp16
__device__ float g_f1[HH * MM];
__device__ float g_f2[HH * MM];
__device__ float g_f1o[MM];
__device__ float g_f2o[MM];

// ----------------------------------------------------------------------------
// helpers
// ----------------------------------------------------------------------------
__device__ __forceinline__ uint32_t smem_u32(const void* p) {
    uint32_t a;
    asm("{ .reg .u64 t; cvta.to.shared.u64 t, %1; cvt.u32.u64 %0, t; }" : "=r"(a) : "l"(p));
    return a;
}

#define CP16(dst, src) asm volatile("cp.async.cg.shared.global [%0], [%1], 16;" :: "r"(dst), "l"(src))
#define CP_COMMIT()    asm volatile("cp.async.commit_group;" ::: "memory")
#define CP_WAIT1()     asm volatile("cp.async.wait_group 1;" ::: "memory")
#define CP_WAIT0()     asm volatile("cp.async.wait_group 0;" ::: "memory")

// ----------------------------------------------------------------------------
// fp16 mma.sync GEMM: C[M,Nc] = A[M,K] @ Bt[N][K]^T
// A: [M][K] half row-major; B: [N][K] half (K contiguous).
// 128x128 CTA tile, 8 warps (64x32), KT=32, 3-stage cp.async, 2 CTAs/SM.
// Smem tiles: 128 rows x 40 halves (32 data + 8 pad) = 20 u32/row, conflict-free.
// EPI: 0 = store f32, 1 = elu -> half, 2 = elu + residual -> f32
// ----------------------------------------------------------------------------
#define KT 32
#define STAGES 3
#define ROW_U 20                         // u32 per smem row (40 halves)
#define TILE_U (128 * ROW_U)             // 2560 u32 = 10240 B
#define STAGE_U (2 * TILE_U)             // A + B
#define GEMM_SMEM (STAGES * STAGE_U * 4) // 61440 B

template <int EPI>
__global__ void __launch_bounds__(256, 2)
hgemm(const __half* __restrict__ A, const __half* __restrict__ B,
      void* __restrict__ Cv, const float* __restrict__ R,
      int K, int ldc, long sA, long sB, long sC, long sC2, int zmod, long sR)
{
    extern __shared__ uint32_t smu[];
    uint32_t sb = smem_u32(smu);
    int tid = threadIdx.x;
    int l = tid & 31;
    int w = tid >> 5;

    int z = blockIdx.z;
    const char* Ag = (const char*)(A + (long)z * sA);
    const char* Bg = (const char*)(B + (long)z * sB);
    long coff = (long)(z % zmod) * sC + (long)(z / zmod) * sC2;
    const float* Rb = (EPI == 2) ? (R + (long)z * sR) : nullptr;

    int brow = blockIdx.y * 128;
    int bcol = blockIdx.x * 128;
    int m0 = (w & 1) * 64;
    int n0 = (w >> 1) * 32;

    float c[4][4][4];
    #pragma unroll
    for (int i = 0; i < 4; i++)
        #pragma unroll
        for (int j = 0; j < 4; j++)
            #pragma unroll
            for (int q = 0; q < 4; q++) c[i][j][q] = 0.0f;

    int nk = K / KT;

    int lrow = tid >> 1;               // 0..127
    int lch  = (tid & 1) * 2;          // 16B chunk index base (0 or 2)

    auto load_stage = [&](int pf) {
        int buf = pf % STAGES;
        uint32_t dA = sb + buf * STAGE_U * 4;
        uint32_t dB = dA + TILE_U * 4;
        long kby = (long)pf * KT * 2;  // byte offset along K
        const char* ga = Ag + (long)(brow + lrow) * K * 2 + kby;
        const char* gb = Bg + (long)(bcol + lrow) * K * 2 + kby;
        uint32_t so = lrow * 80;
        #pragma unroll
        for (int i = 0; i < 2; i++)
            CP16(dA + so + (lch + i) * 16, ga + (lch + i) * 16);
        #pragma unroll
        for (int i = 0; i < 2; i++)
            CP16(dB + so + (lch + i) * 16, gb + (lch + i) * 16);
        CP_COMMIT();
    };

    load_stage(0);
    load_stage(1);

    int fr = m0 + (l >> 2);
    int fc = n0 + (l >> 2);
    int kq = l & 3;

    for (int s = 0; s < nk; s++) {
        if (s + 1 < nk) { CP_WAIT1(); } else { CP_WAIT0(); }
        __syncthreads();
        if (s + 2 < nk) load_stage(s + 2);

        const uint32_t* As = smu + (s % STAGES) * STAGE_U;
        const uint32_t* Bs = As + TILE_U;

        #pragma unroll
        for (int ks = 0; ks < 2; ks++) {
            int kb = ks * 8 + kq;
            uint32_t a[4][4], b[4][2];
            #pragma unroll
            for (int mi = 0; mi < 4; mi++) {
                int r = fr + mi * 16;
                a[mi][0] = As[r * ROW_U + kb];
                a[mi][1] = As[(r + 8) * ROW_U + kb];
                a[mi][2] = As[r * ROW_U + kb + 4];
                a[mi][3] = As[(r + 8) * ROW_U + kb + 4];
            }
            #pragma unroll
            for (int ni = 0; ni < 4; ni++) {
                int cn = fc + ni * 8;
                b[ni][0] = Bs[cn * ROW_U + kb];
                b[ni][1] = Bs[cn * ROW_U + kb + 4];
            }
            #pragma unroll
            for (int mi = 0; mi < 4; mi++)
                #pragma unroll
                for (int ni = 0; ni < 4; ni++)
                    asm volatile(
                        "mma.sync.aligned.m16n8k16.row.col.f32.f16.f16.f32 "
                        "{%0,%1,%2,%3}, {%4,%5,%6,%7}, {%8,%9}, {%0,%1,%2,%3};"
                        : "+f"(c[mi][ni][0]), "+f"(c[mi][ni][1]),
                          "+f"(c[mi][ni][2]), "+f"(c[mi][ni][3])
                        : "r"(a[mi][0]), "r"(a[mi][1]), "r"(a[mi][2]), "r"(a[mi][3]),
                          "r"(b[ni][0]), "r"(b[ni][1]));
        }
    }

    // epilogue (row-major C)
    #pragma unroll
    for (int mi = 0; mi < 4; mi++) {
        #pragma unroll
        for (int hh = 0; hh < 2; hh++) {
            long rg = brow + m0 + mi * 16 + (l >> 2) + hh * 8;
            #pragma unroll
            for (int ni = 0; ni < 4; ni++) {
                float v0 = c[mi][ni][hh * 2 + 0];
                float v1 = c[mi][ni][hh * 2 + 1];
                if (EPI >= 1) {
                    v0 = (v0 > 0.0f) ? v0 : expm1f(v0);
                    v1 = (v1 > 0.0f) ? v1 : expm1f(v1);
                }
                long ci = coff + rg * ldc + bcol + n0 + ni * 8 + (l & 3) * 2;
                if (EPI == 1) {
                    __half2* Ch = (__half2*)((__half*)Cv + ci);
                    *Ch = __floats2half2_rn(v0, v1);
                } else {
                    float* Cf = (float*)Cv + ci;
                    if (EPI == 2) {
                        float2 rv = *(const float2*)&Rb[ci - coff];
                        v0 += rv.x; v1 += rv.y;
                    }
                    float2 o; o.x = v0; o.y = v1;
                    *(float2*)Cf = o;
                }
            }
        }
    }
}

// ----------------------------------------------------------------------------
// f32 -> f16 elementwise convert
// ----------------------------------------------------------------------------
__global__ void __launch_bounds__(256)
f2h_kernel(const float4* __restrict__ in, __half2* __restrict__ out, long n4)
{
    long i = (long)blockIdx.x * 256 + threadIdx.x;
    if (i < n4) {
        float4 v = in[i];
        out[i * 2 + 0] = __floats2half2_rn(v.x, v.y);
        out[i * 2 + 1] = __floats2half2_rn(v.z, v.w);
    }
}

// ----------------------------------------------------------------------------
// batched transpose + convert: f32 [z][R][C] -> f16 [z][C][R]
// ----------------------------------------------------------------------------
__global__ void __launch_bounds__(256)
transpose_h_kernel(const float* __restrict__ in, __half* __restrict__ out,
                   int R, int C)
{
    __shared__ float t[32][33];
    long z = blockIdx.z;
    in  += z * (long)R * C;
    out += z * (long)R * C;
    int x = blockIdx.x * 32;
    int y = blockIdx.y * 32;
    int tx = threadIdx.x & 31, ty = threadIdx.x >> 5;
    #pragma unroll
    for (int i = 0; i < 32; i += 8)
        t[ty + i][tx] = in[(long)(y + ty + i) * C + x + tx];
    __syncthreads();
    #pragma unroll
    for (int i = 0; i < 32; i += 8)
        out[(long)(x + ty + i) * R + y + tx] = __float2half_rn(t[tx][ty + i]);
}

// ----------------------------------------------------------------------------
// fast exp (FMA only)
// ----------------------------------------------------------------------------
__device__ __forceinline__ float fexp(float x) {
    float y = x * 1.4426950408889634f;
    y = fmaxf(y, -126.0f);
    float r = y + 12582912.0f;
    float fn = r - 12582912.0f;
    int   n  = (int)fn;
    float f  = y - fn;
    float p = 1.3400e-3f;
    p = fmaf(p, f, 9.6784351e-3f);
    p = fmaf(p, f, 5.5503426e-2f);
    p = fmaf(p, f, 2.4022652e-1f);
    p = fmaf(p, f, 6.9314718e-1f);
    p = fmaf(p, f, 1.0f);
    return __int_as_float(__float_as_int(p) + (n << 23));
}

// ----------------------------------------------------------------------------
// f1/f2: warp-per-(row,head) dual dot products
// ----------------------------------------------------------------------------
__global__ void __launch_bounds__(256)
fvec_kernel(const float* __restrict__ Wh, const float* __restrict__ a,
            float* __restrict__ f1, float* __restrict__ f2, int nh)
{
    int gw = (blockIdx.x * 256 + threadIdx.x) >> 5;
    int l = threadIdx.x & 31;
    if (gw >= MM * nh) return;
    int h = gw / MM;
    const float4* wv = (const float4*)(Wh + (long)gw * DD);
    const float4* a1 = (const float4*)(a + (long)h * 2 * DD);
    const float4* a2 = (const float4*)(a + (long)h * 2 * DD + DD);
    float s1 = 0.0f, s2 = 0.0f;
    #pragma unroll
    for (int i = 0; i < DD / 128; i++) {
        int idx = l + i * 32;
        float4 v = wv[idx], x = a1[idx], y = a2[idx];
        s1 += v.x * x.x + v.y * x.y + v.z * x.z + v.w * x.w;
        s2 += v.x * y.x + v.y * y.y + v.z * y.z + v.w * y.w;
    }
    #pragma unroll
    for (int o = 16; o; o >>= 1) {
        s1 += __shfl_xor_sync(0xFFFFFFFFu, s1, o);
        s2 += __shfl_xor_sync(0xFFFFFFFFu, s2, o);
    }
    if (l == 0) { f1[gw] = s1; f2[gw] = s2; }
}

// ----------------------------------------------------------------------------
// masked softmax rows -> P (fp16); scores kept in registers
// ----------------------------------------------------------------------------
__global__ void __launch_bounds__(256)
attn_rows_kernel(const int* __restrict__ adj,
                 const float* __restrict__ f1, const float* __restrict__ f2,
                 __half* __restrict__ P, int nheads)
{
    int r = blockIdx.x;
    int b = r >> 10;
    int t = threadIdx.x;
    int l = t & 31, w = t >> 5;

    __shared__ float wmax[8];
    __shared__ float wsum[8];

    int av[NN / 256];
    const int* arow = adj + (long)r * NN;
    #pragma unroll
    for (int k = 0; k < NN / 256; k++) av[k] = arow[t + k * 256];

    for (int h = 0; h < nheads; h++) {
        float f1v = f1[(long)h * MM + r];
        const float* f2h = f2 + (long)h * MM + (long)b * NN;

        float sv[NN / 256];
        float lmax = -INFINITY;
        #pragma unroll
        for (int k = 0; k < NN / 256; k++) {
            float s = f1v + f2h[t + k * 256];
            s = (s > 0.0f) ? s : ALPHA_LRELU * s;
            sv[k] = s;
            if (av[k]) lmax = fmaxf(lmax, s);
        }
        #pragma unroll
        for (int o = 16; o; o >>= 1)
            lmax = fmaxf(lmax, __shfl_xor_sync(0xFFFFFFFFu, lmax, o));
        if (l == 0) wmax[w] = lmax;
        __syncthreads();
        float m = wmax[0];
        #pragma unroll
        for (int q = 1; q < 8; q++) m = fmaxf(m, wmax[q]);

        float lsum = 0.0f;
        #pragma unroll
        for (int k = 0; k < NN / 256; k++) {
            float e = av[k] ? fexp(sv[k] - m) : 0.0f;
            sv[k] = e;
            lsum += e;
        }
        #pragma unroll
        for (int o = 16; o; o >>= 1)
            lsum += __shfl_xor_sync(0xFFFFFFFFu, lsum, o);
        if (l == 0) wsum[w] = lsum;
        __syncthreads();
        float den = 0.0f;
        #pragma unroll
        for (int q = 0; q < 8; q++) den += wsum[q];
        float rd = 1.0f / den;

        __half* Prow = P + (((long)h * BB + b) * NN + (r & 1023)) * NN;
        #pragma unroll
        for (int k = 0; k < NN / 256; k++)
            Prow[t + k * 256] = __float2half_rn(sv[k] * rd);
        __syncthreads();
    }
}

// ----------------------------------------------------------------------------
// classifier: warp-per-row
// ----------------------------------------------------------------------------
__global__ void __launch_bounds__(256)
classifier_kernel(const float* __restrict__ yy, const float* __restrict__ wc,
                  const float* __restrict__ bc, const float* __restrict__ mask,
                  float* __restrict__ scores)
{
    int gw = (blockIdx.x * 256 + threadIdx.x) >> 5;
    int l = threadIdx.x & 31;
    if (gw >= MM) return;
    const float4* y = (const float4*)(yy + (long)gw * DD);
    const float4* wv = (const float4*)wc;
    float s = 0.0f;
    #pragma unroll
    for (int i = 0; i < DD / 128; i++) {
        int idx = l + i * 32;
        float4 a = y[idx], b = wv[idx];
        s += a.x * b.x + a.y * b.y + a.z * b.z + a.w * b.w;
    }
    #pragma unroll
    for (int o = 16; o; o >>= 1) s += __shfl_xor_sync(0xFFFFFFFFu, s, o);
    if (l == 0) {
        float v = s + bc[0];
        scores[gw] = (1.0f / (1.0f + expf(-v))) * mask[gw];
    }
}

// ----------------------------------------------------------------------------
// launch
// ----------------------------------------------------------------------------
extern "C" void kernel_launch(void* const* d_in, const int* in_sizes, int n_in,
                              void* d_out, int out_size)
{
    const float* input_emb = (const float*)d_in[0];
    const int*   adj       = (const int*)d_in[1];
    const float* mask_node = (const float*)d_in[2];
    const float* W_heads   = (const float*)d_in[3];
    const float* a_heads   = (const float*)d_in[4];
    const float* W_out     = (const float*)d_in[5];
    const float* a_out     = (const float*)d_in[6];
    const float* w_cls     = (const float*)d_in[7];
    const float* b_cls     = (const float*)d_in[8];

    float* yy     = (float*)d_out;
    float* scores = (float*)d_out + (long)MM * DD;

    __half *p_X16, *p_W16T, *p_Wo16T, *p_WhT16, *p_xx16, *p_WhoT16, *p_P16;
    float *p_Wh, *p_Who, *p_f1, *p_f2, *p_f1o, *p_f2o;
    cudaGetSymbolAddress((void**)&p_X16,   g_X16);
    cudaGetSymbolAddress((void**)&p_W16T,  g_W16T);
    cudaGetSymbolAddress((void**)&p_Wo16T, g_Wo16T);
    cudaGetSymbolAddress((void**)&p_Wh,    g_Wh);
    cudaGetSymbolAddress((void**)&p_WhT16, g_WhT16);
    cudaGetSymbolAddress((void**)&p_xx16,  g_xx16);
    cudaGetSymbolAddress((void**)&p_Who,   g_Who);
    cudaGetSymbolAddress((void**)&p_WhoT16, g_WhoT16);
    cudaGetSymbolAddress((void**)&p_P16,   g_P16);
    cudaGetSymbolAddress((void**)&p_f1,    g_f1);
    cudaGetSymbolAddress((void**)&p_f2,    g_f2);
    cudaGetSymbolAddress((void**)&p_f1o,   g_f1o);
    cudaGetSymbolAddress((void**)&p_f2o,   g_f2o);

    cudaFuncSetAttribute(hgemm<0>, cudaFuncAttributeMaxDynamicSharedMemorySize, GEMM_SMEM);
    cudaFuncSetAttribute(hgemm<1>, cudaFuncAttributeMaxDynamicSharedMemorySize, GEMM_SMEM);
    cudaFuncSetAttribute(hgemm<2>, cudaFuncAttributeMaxDynamicSharedMemorySize, GEMM_SMEM);

    const int ZBIG = 1 << 30;

    // 0) convert X -> fp16; transpose+convert W_heads, W_out
    {
        long n4 = (long)MM * DD / 4;
        f2h_kernel<<<(unsigned)((n4 + 255) / 256), 256>>>((const float4*)input_emb, (__half2*)p_X16, n4);
    }
    transpose_h_kernel<<<dim3(DD / 32, DD / 32, HH), 256>>>(W_heads, p_W16T, DD, DD);
    transpose_h_kernel<<<dim3(DD / 32, (HH * DD) / 32, 1), 256>>>(W_out, p_Wo16T, HH * DD, DD);

    // 1) Wh[h] = X @ W_heads[h]  -> f32
    hgemm<0><<<dim3(DD / 128, MM / 128, HH), 256, GEMM_SMEM>>>(
        p_X16, p_W16T, p_Wh, nullptr, DD, DD,
        0L, (long)DD * DD, (long)MM * DD, 0L, ZBIG, 0L);

    // 2) f1/f2
    fvec_kernel<<<(MM * HH * 32 + 255) / 256, 256>>>(p_Wh, a_heads, p_f1, p_f2, HH);

    // 3) attention probs -> fp16
    attn_rows_kernel<<<MM, 256>>>(adj, p_f1, p_f2, p_P16, HH);

    // 3b) Wh^T per (h,b): f32 [1024][768] -> f16 [768][1024]
    transpose_h_kernel<<<dim3(DD / 32, NN / 32, HH * BB), 256>>>(p_Wh, p_WhT16, NN, DD);

    // 4) xx = elu(P @ Wh) -> fp16   (z = h*BB+b)
    hgemm<1><<<dim3(DD / 128, NN / 128, HH * BB), 256, GEMM_SMEM>>>(
        p_P16, p_WhT16, p_xx16, nullptr, NN, HH * DD,
        (long)NN * NN, (long)DD * NN,
        (long)NN * HH * DD, (long)DD, BB, 0L);

    // 5) Who = xx @ W_out -> f32   (K=3072)
    hgemm<0><<<dim3(DD / 128, MM / 128, 1), 256, GEMM_SMEM>>>(
        p_xx16, p_Wo16T, p_Who, nullptr, HH * DD, DD,
        0L, 0L, 0L, 0L, ZBIG, 0L);

    // 6) f1o/f2o
    fvec_kernel<<<(MM * 32 + 255) / 256, 256>>>(p_Who, a_out, p_f1o, p_f2o, 1);

    // 7) out-layer attention probs -> fp16
    attn_rows_kernel<<<MM, 256>>>(adj, p_f1o, p_f2o, p_P16, 1);

    // 7b) Who^T per b
    transpose_h_kernel<<<dim3(DD / 32, NN / 32, BB), 256>>>(p_Who, p_WhoT16, NN, DD);

    // 8) yy = elu(P @ Who) + input_emb -> f32
    hgemm<2><<<dim3(DD / 128, NN / 128, BB), 256, GEMM_SMEM>>>(
        p_P16, p_WhoT16, yy, input_emb, NN, DD,
        (long)NN * NN, (long)DD * NN,
        (long)NN * DD, 0L, ZBIG, (long)NN * DD);

    // 9) classifier
    classifier_kernel<<<(MM * 32 + 255) / 256, 256>>>(yy, w_cls, b_cls, mask_node, scores);

    (void)in_sizes; (void)n_in; (void)out_size;
}